// round 12
// baseline (speedup 1.0000x reference)
#include <cuda_runtime.h>
#include <math_constants.h>
#include <cuda_fp16.h>
#include <cstdint>

#define B_    2
#define S_    2048
#define NX_   1024
#define NST   1024
#define NH    16
#define HD    64
#define MROWS 4096
#define C3    3072

// Scratch (no allocations allowed)
__device__ __half g_qkvh[MROWS * C3];   // [4096, 3072] q|k|v fp16
__device__ __half g_attnh[MROWS * NST]; // merged heads fp16
__device__ __half g_xh[MROWS * NX_];    // x fp16
__device__ __half g_wcth[C3 * NX_];     // w_c^T fp16
__device__ __half g_wpth[NST * NX_];    // w_p^T fp16

__device__ __forceinline__ uint32_t smem_u32(const void* p) {
    uint32_t a;
    asm("{ .reg .u64 t; cvta.to.shared.u64 t, %1; cvt.u32.u64 %0, t; }"
        : "=r"(a) : "l"(p));
    return a;
}
__device__ __forceinline__ uint32_t pack_h2(float lo, float hi) {
    uint32_t r;
    asm("cvt.rn.f16x2.f32 %0, %1, %2;" : "=r"(r) : "f"(hi), "f"(lo));
    return r;
}
__device__ __forceinline__ uint32_t ex2_h2(uint32_t h2) {
    uint32_t r;
    asm("ex2.approx.f16x2 %0, %1;" : "=r"(r) : "r"(h2));
    return r;
}
__device__ __forceinline__ float2 h2_to_f2(uint32_t h2) {
    __half2 h = *reinterpret_cast<__half2*>(&h2);
    return __half22float2(h);
}
#define CP_ASYNC16(smaddr, gptr) \
    asm volatile("cp.async.cg.shared.global [%0], [%1], 16;" \
                 :: "r"(smaddr), "l"(gptr) : "memory")
#define CP_COMMIT() asm volatile("cp.async.commit_group;" ::: "memory")
#define CP_WAIT1()  asm volatile("cp.async.wait_group 1;" ::: "memory")

#define MMA_F16(acc, a, b0, b1)                                                \
    asm volatile(                                                              \
        "mma.sync.aligned.m16n8k16.row.col.f32.f16.f16.f32 "                   \
        "{%0,%1,%2,%3}, {%4,%5,%6,%7}, {%8,%9}, {%0,%1,%2,%3};"                \
        : "+f"((acc)[0]), "+f"((acc)[1]), "+f"((acc)[2]), "+f"((acc)[3])       \
        : "r"((a)[0]), "r"((a)[1]), "r"((a)[2]), "r"((a)[3]),                  \
          "r"(b0), "r"(b1))

#define LDMX4(r0, r1, r2, r3, addr)                                            \
    asm volatile(                                                              \
        "ldmatrix.sync.aligned.m8n8.x4.shared.b16 {%0,%1,%2,%3}, [%4];"        \
        : "=r"(r0), "=r"(r1), "=r"(r2), "=r"(r3) : "r"(addr))

#define LDMX4T(r0, r1, r2, r3, addr)                                           \
    asm volatile(                                                              \
        "ldmatrix.sync.aligned.m8n8.x4.trans.shared.b16 {%0,%1,%2,%3}, [%4];"  \
        : "=r"(r0), "=r"(r1), "=r"(r2), "=r"(r3) : "r"(addr))

// ---------------------------------------------------------------------------
// Prep kernels
// ---------------------------------------------------------------------------
__global__ __launch_bounds__(256) void round_f16_kernel(
    const float* __restrict__ in, __half* __restrict__ out, int n4)
{
    int i = blockIdx.x * 256 + threadIdx.x;
    if (i < n4) {
        float4 v = ((const float4*)in)[i];
        uint2 o;
        o.x = pack_h2(v.x, v.y);
        o.y = pack_h2(v.z, v.w);
        ((uint2*)out)[i] = o;
    }
}

__global__ __launch_bounds__(256) void transpose_f16_kernel(
    const float* __restrict__ W, __half* __restrict__ WT, int K, int N)
{
    __shared__ float t[32][33];
    const int tx = threadIdx.x, ty = threadIdx.y;
    const int n0 = blockIdx.x * 32, k0 = blockIdx.y * 32;
    #pragma unroll
    for (int i = 0; i < 32; i += 8)
        t[ty + i][tx] = W[(size_t)(k0 + ty + i) * N + n0 + tx];
    __syncthreads();
    #pragma unroll
    for (int i = 0; i < 32; i += 8)
        WT[(size_t)(n0 + ty + i) * K + k0 + tx] = __float2half(t[tx][ty + i]);
}

// ---------------------------------------------------------------------------
// fp16 mma GEMM (R9/R11 config: BM=128, BN=128, BK=64, 8 warps, ping-pong
// frags, 3-stage cp.async, one barrier per chunk, 2 CTA/SM).
// ---------------------------------------------------------------------------
#define GBM 128
#define GBN 128
#define GBK 64
#define HP  72
#define TILE_H (128 * HP)
#define GEMM_SMEM (6 * TILE_H * 2)        // 110592 B

__global__ __launch_bounds__(256, 2) void gemm_f16_kernel(
    const __half* __restrict__ A, const __half* __restrict__ BT,
    const float* __restrict__ bias, float* __restrict__ C,
    __half* __restrict__ QH, int qkv_mode,
    int M, int N, int K)
{
    extern __shared__ __align__(16) __half smh[];
    const uint32_t smb = smem_u32(smh);

    const int tid = threadIdx.x;
    const int wid = tid >> 5, lane = tid & 31;
    const int gid = lane >> 2, tig = lane & 3;
    const int warp_m = wid & 1, warp_n = wid >> 1;

    const int m0 = blockIdx.y * GBM;
    const int n0 = blockIdx.x * GBN;

    const int cr = tid >> 1;
    const int cb = (tid & 1) << 3;

    const __half* Ap = A + (size_t)m0 * K;
    const __half* Bp = BT + (size_t)n0 * K;

    const int nchunk = K / GBK;

    const int mrow = lane & 15;
    const int kcolA = (lane >> 4) << 3;
    const int nrow = ((lane >> 4) << 3) + (lane & 7);
    const int kcolB = ((lane >> 3) & 1) << 3;

    float acc[4][4][4];
    #pragma unroll
    for (int i = 0; i < 4; i++)
        #pragma unroll
        for (int j = 0; j < 4; j++)
            #pragma unroll
            for (int r = 0; r < 4; r++) acc[i][j][r] = 0.0f;

    #define PREFETCH(kc, st) do {                                               \
        const uint32_t abase = smb + (st) * TILE_H * 2;                         \
        const uint32_t bbase = smb + (3 + (st)) * TILE_H * 2;                   \
        _Pragma("unroll")                                                       \
        for (int s = 0; s < 4; s++) {                                           \
            const int col = cb + s * 16;                                        \
            CP_ASYNC16(abase + (cr * HP + col) * 2,                             \
                       Ap + (size_t)cr * K + (kc) * GBK + col);                 \
            CP_ASYNC16(bbase + (cr * HP + col) * 2,                             \
                       Bp + (size_t)cr * K + (kc) * GBK + col);                 \
        }                                                                       \
    } while (0)

    PREFETCH(0, 0); CP_COMMIT();
    PREFETCH(1, 1); CP_COMMIT();

    uint32_t af[2][4][4], bf[2][2][4];

    #define LOAD_FRAGS(buf, Asb_, Bsb_, k0_) do {                               \
        _Pragma("unroll")                                                       \
        for (int i = 0; i < 4; i++) {                                           \
            const uint32_t a_ =                                                 \
                (Asb_) + ((warp_m * 64 + i * 16 + mrow) * HP + (k0_) + kcolA) * 2; \
            LDMX4(af[buf][i][0], af[buf][i][1], af[buf][i][2], af[buf][i][3], a_); \
        }                                                                       \
        _Pragma("unroll")                                                       \
        for (int j = 0; j < 2; j++) {                                           \
            const uint32_t b_ =                                                 \
                (Bsb_) + ((warp_n * 32 + j * 16 + nrow) * HP + (k0_) + kcolB) * 2; \
            LDMX4(bf[buf][j][0], bf[buf][j][1], bf[buf][j][2], bf[buf][j][3], b_); \
        }                                                                       \
    } while (0)

    #define MMA_GROUP(buf) do {                                                 \
        _Pragma("unroll")                                                       \
        for (int j = 0; j < 2; j++)                                             \
            _Pragma("unroll")                                                   \
            for (int i = 0; i < 4; i++) {                                       \
                MMA_F16(acc[i][2 * j],     af[buf][i], bf[buf][j][0], bf[buf][j][1]); \
                MMA_F16(acc[i][2 * j + 1], af[buf][i], bf[buf][j][2], bf[buf][j][3]); \
            }                                                                   \
    } while (0)

    for (int kc = 0; kc < nchunk; kc++) {
        const int st = kc % 3;
        CP_WAIT1();
        __syncthreads();

        const uint32_t Asb = smb + st * TILE_H * 2;
        const uint32_t Bsb = smb + (3 + st) * TILE_H * 2;

        LOAD_FRAGS(0, Asb, Bsb, 0);
        if (kc + 2 < nchunk) { PREFETCH(kc + 2, (kc + 2) % 3); }
        CP_COMMIT();

        #pragma unroll
        for (int g = 0; g < 4; g++) {
            if (g < 3) LOAD_FRAGS((g + 1) & 1, Asb, Bsb, (g + 1) * 16);
            MMA_GROUP(g & 1);
        }
    }

    if (qkv_mode) {
        #pragma unroll
        for (int i = 0; i < 4; i++) {
            const int r0 = m0 + warp_m * 64 + i * 16 + gid;
            #pragma unroll
            for (int j = 0; j < 4; j++) {
                const int col = n0 + warp_n * 32 + j * 8 + 2 * tig;
                const float bx = bias[col], by = bias[col + 1];
                *(uint32_t*)(QH + (size_t)r0 * C3 + col) =
                    pack_h2(acc[i][j][0] + bx, acc[i][j][1] + by);
                *(uint32_t*)(QH + (size_t)(r0 + 8) * C3 + col) =
                    pack_h2(acc[i][j][2] + bx, acc[i][j][3] + by);
            }
        }
    } else {
        #pragma unroll
        for (int i = 0; i < 4; i++) {
            const int r0 = m0 + warp_m * 64 + i * 16 + gid;
            #pragma unroll
            for (int j = 0; j < 4; j++) {
                const int col = n0 + warp_n * 32 + j * 8 + 2 * tig;
                const float bx = bias[col], by = bias[col + 1];
                float2 v0 = make_float2(acc[i][j][0] + bx, acc[i][j][1] + by);
                float2 v1 = make_float2(acc[i][j][2] + bx, acc[i][j][3] + by);
                *(float2*)(C + (size_t)r0 * N + col) = v0;
                *(float2*)(C + (size_t)(r0 + 8) * N + col) = v1;
            }
        }
    }
}

// ---------------------------------------------------------------------------
// Flash attention, fp16 mma + f16x2 exp. NOW: 3-stage KV pipeline with ONE
// barrier per tile (prefetch at top overwrites the stage consumed two
// iterations ago — safe after the top barrier). Batch selected by param so
// the two batches can be launched on different positions for overlap.
// Smem (halves): Q 128x72 | K 3x 64x72 | V 3x 64x72 = 73728 B. 2 CTA/SM.
// ---------------------------------------------------------------------------
#define KOFF 9216                            // halves
#define KVSTG 4608                           // halves per K or V stage
#define VOFF  (KOFF + 3 * KVSTG)
#define FLASH_SMEM ((VOFF + 3 * KVSTG) * 2)  // 73728 B

__global__ __launch_bounds__(256, 2) void flash_f16_kernel(
    const __half* __restrict__ qkvh, __half* __restrict__ attnh, int bsel)
{
    extern __shared__ __align__(16) __half smh[];
    const uint32_t smb = smem_u32(smh);

    const int qb = (int)gridDim.x - 1 - (int)blockIdx.x;  // heavy first
    const int h  = blockIdx.y;
    const int b  = bsel;
    const int tid = threadIdx.x;
    const int wid = tid >> 5, lane = tid & 31;
    const int gid = lane >> 2, tig = lane & 3;

    const int hoff = h * HD;
    const __half* qptr = qkvh + (size_t)b * S_ * C3 + (size_t)qb * 128 * C3 + hoff;
    const __half* kptr = qkvh + (size_t)b * S_ * C3 + NST + hoff;
    const __half* vptr = qkvh + (size_t)b * S_ * C3 + 2 * NST + hoff;
    const float qls = 0.125f * 1.4426950408889634f;   // rsqrt(64)*log2(e)

    // Q tile (group 0): 128 rows x 64 halves
    {
        const int r = tid >> 1;
        const int cb = (tid & 1) << 3;
        #pragma unroll
        for (int s = 0; s < 4; s++) {
            const int c = cb + s * 16;
            CP_ASYNC16(smb + (r * HP + c) * 2, qptr + (size_t)r * C3 + c);
        }
        CP_COMMIT();
    }

    #define PREFETCH_KV(kt, st) do {                                            \
        const uint32_t kb = smb + (KOFF + (st) * KVSTG) * 2;                     \
        const uint32_t vb = smb + (VOFF + (st) * KVSTG) * 2;                     \
        const int r_ = tid >> 2;                                                 \
        _Pragma("unroll")                                                        \
        for (int s_ = 0; s_ < 2; s_++) {                                         \
            const int c_ = ((tid & 3) + 4 * s_) * 8;                             \
            CP_ASYNC16(kb + (r_ * HP + c_) * 2,                                  \
                       kptr + (size_t)((kt) * 64 + r_) * C3 + c_);               \
            CP_ASYNC16(vb + (r_ * HP + c_) * 2,                                  \
                       vptr + (size_t)((kt) * 64 + r_) * C3 + c_);               \
        }                                                                        \
    } while (0)

    PREFETCH_KV(0, 0); CP_COMMIT();
    PREFETCH_KV(1, 1); CP_COMMIT();

    float oacc[8][4];
    #pragma unroll
    for (int nb = 0; nb < 8; nb++)
        #pragma unroll
        for (int r = 0; r < 4; r++) oacc[nb][r] = 0.0f;
    float m0 = -1e30f, m1 = -1e30f, l0 = 0.0f, l1 = 0.0f;

    const int pr = wid * 16 + gid;
    const int grow0 = qb * 128 + pr;
    const int grow1 = grow0 + 8;

    const int mrow = lane & 15;
    const int kcolA = (lane >> 4) << 3;
    const int nrow = ((lane >> 4) << 3) + (lane & 7);
    const int kcolB = ((lane >> 3) & 1) << 3;
    const int l16 = lane & 15;
    const int chalf = (lane >> 4) << 3;

    const int nkt = 2 * qb + 2;
    for (int kt = 0; kt < nkt; kt++) {
        const int st = kt % 3;
        CP_WAIT1();
        __syncthreads();      // all warps done with tile kt-1; stage kt data in

        // prefetch into stage (kt+2)%3, consumed at iteration kt-1
        if (kt + 2 < nkt) { PREFETCH_KV(kt + 2, (kt + 2) % 3); }
        CP_COMMIT();

        const uint32_t Ksb = smb + (KOFF + st * KVSTG) * 2;
        const uint32_t vbase = smb + (VOFF + st * KVSTG) * 2;

        // S = Q K^T (fp16 mma, f32 acc) — raw, unscaled
        float sacc[8][4];
        #pragma unroll
        for (int nb = 0; nb < 8; nb++)
            #pragma unroll
            for (int r = 0; r < 4; r++) sacc[nb][r] = 0.0f;

        #pragma unroll
        for (int k0 = 0; k0 < 64; k0 += 16) {
            uint32_t qa[4];
            LDMX4(qa[0], qa[1], qa[2], qa[3],
                  smb + ((wid * 16 + mrow) * HP + k0 + kcolA) * 2);
            #pragma unroll
            for (int j = 0; j < 4; j++) {
                uint32_t b0, b1, b2, b3;
                LDMX4(b0, b1, b2, b3,
                      Ksb + ((j * 16 + nrow) * HP + k0 + kcolB) * 2);
                MMA_F16(sacc[2 * j],     qa, b0, b1);
                MMA_F16(sacc[2 * j + 1], qa, b2, b3);
            }
        }

        // causal mask on raw scores (diag-crossing tiles only)
        if (kt >= 2 * qb) {
            #pragma unroll
            for (int nb = 0; nb < 8; nb++) {
                const int c = kt * 64 + nb * 8 + 2 * tig;
                if (c > grow0)     sacc[nb][0] = -1e30f;
                if (c + 1 > grow0) sacc[nb][1] = -1e30f;
                if (c > grow1)     sacc[nb][2] = -1e30f;
                if (c + 1 > grow1) sacc[nb][3] = -1e30f;
            }
        }

        // row max over raw scores; to scaled (log2) domain once
        float mx0 = -1e30f, mx1 = -1e30f;
        #pragma unroll
        for (int nb = 0; nb < 8; nb++) {
            mx0 = fmaxf(mx0, fmaxf(sacc[nb][0], sacc[nb][1]));
            mx1 = fmaxf(mx1, fmaxf(sacc[nb][2], sacc[nb][3]));
        }
        mx0 = fmaxf(mx0, __shfl_xor_sync(0xffffffffu, mx0, 1));
        mx0 = fmaxf(mx0, __shfl_xor_sync(0xffffffffu, mx0, 2));
        mx1 = fmaxf(mx1, __shfl_xor_sync(0xffffffffu, mx1, 1));
        mx1 = fmaxf(mx1, __shfl_xor_sync(0xffffffffu, mx1, 2));
        const float mn0 = fmaxf(m0, mx0 * qls), mn1 = fmaxf(m1, mx1 * qls);
        const float al0 = exp2f(m0 - mn0), al1 = exp2f(m1 - mn1);

        // P = exp2(s*qls - mn) via ex2.approx.f16x2
        uint32_t plo[8], phi[8];
        float sum0 = 0.0f, sum1 = 0.0f;
        #pragma unroll
        for (int nb = 0; nb < 8; nb++) {
            const float d0 = fmaf(sacc[nb][0], qls, -mn0);
            const float d1 = fmaf(sacc[nb][1], qls, -mn0);
            const float d2 = fmaf(sacc[nb][2], qls, -mn1);
            const float d3 = fmaf(sacc[nb][3], qls, -mn1);
            plo[nb] = ex2_h2(pack_h2(d0, d1));
            phi[nb] = ex2_h2(pack_h2(d2, d3));
            const float2 f0 = h2_to_f2(plo[nb]);
            const float2 f1 = h2_to_f2(phi[nb]);
            sum0 += f0.x + f0.y;
            sum1 += f1.x + f1.y;
        }
        sum0 += __shfl_xor_sync(0xffffffffu, sum0, 1);
        sum0 += __shfl_xor_sync(0xffffffffu, sum0, 2);
        sum1 += __shfl_xor_sync(0xffffffffu, sum1, 1);
        sum1 += __shfl_xor_sync(0xffffffffu, sum1, 2);
        l0 = l0 * al0 + sum0;
        l1 = l1 * al1 + sum1;
        m0 = mn0; m1 = mn1;
        #pragma unroll
        for (int nb = 0; nb < 8; nb++) {
            oacc[nb][0] *= al0; oacc[nb][1] *= al0;
            oacc[nb][2] *= al1; oacc[nb][3] *= al1;
        }

        // PV: P fragments straight from plo/phi; V via ldmatrix.x4.trans
        #pragma unroll
        for (int nbp = 0; nbp < 4; nbp++) {
            uint32_t pa[4];
            pa[0] = plo[2 * nbp];
            pa[1] = phi[2 * nbp];
            pa[2] = plo[2 * nbp + 1];
            pa[3] = phi[2 * nbp + 1];
            const int k0 = nbp * 16;
            #pragma unroll
            for (int np = 0; np < 4; np++) {
                const int n0c = np * 16;
                uint32_t b0, b1, b2, b3;
                const uint32_t va =
                    vbase + ((k0 + l16) * HP + n0c + chalf) * 2;
                LDMX4T(b0, b1, b2, b3, va);
                MMA_F16(oacc[2 * np],     pa, b0, b1);
                MMA_F16(oacc[2 * np + 1], pa, b2, b3);
            }
        }
    }

    const float inv0 = 1.0f / l0, inv1 = 1.0f / l1;
    __half* orow0 = attnh + ((size_t)b * S_ + grow0) * NST + hoff;
    __half* orow1 = attnh + ((size_t)b * S_ + grow1) * NST + hoff;
    #pragma unroll
    for (int nb = 0; nb < 8; nb++) {
        const int c = nb * 8 + 2 * tig;
        *(uint32_t*)(orow0 + c) = pack_h2(oacc[nb][0] * inv0, oacc[nb][1] * inv0);
        *(uint32_t*)(orow1 + c) = pack_h2(oacc[nb][2] * inv1, oacc[nb][3] * inv1);
    }
}

// ---------------------------------------------------------------------------
// Streams/events created ONCE at static-init time (before the harness's mem
// checkpoints), so captures only see event record/wait — the documented
// cross-stream capture pattern. Fallback: if creation fails, run sequential.
// ---------------------------------------------------------------------------
static cudaStream_t g_sA = nullptr, g_sB = nullptr;
static cudaEvent_t g_evFork, g_evWc, g_evWp, g_evF0, g_evP0;
static bool g_streams_ok = false;

struct StreamInit {
    StreamInit() {
        bool ok = true;
        ok &= (cudaStreamCreateWithFlags(&g_sA, cudaStreamNonBlocking) == cudaSuccess);
        ok &= (cudaStreamCreateWithFlags(&g_sB, cudaStreamNonBlocking) == cudaSuccess);
        ok &= (cudaEventCreateWithFlags(&g_evFork, cudaEventDisableTiming) == cudaSuccess);
        ok &= (cudaEventCreateWithFlags(&g_evWc, cudaEventDisableTiming) == cudaSuccess);
        ok &= (cudaEventCreateWithFlags(&g_evWp, cudaEventDisableTiming) == cudaSuccess);
        ok &= (cudaEventCreateWithFlags(&g_evF0, cudaEventDisableTiming) == cudaSuccess);
        ok &= (cudaEventCreateWithFlags(&g_evP0, cudaEventDisableTiming) == cudaSuccess);
        g_streams_ok = ok;
    }
};
static StreamInit g_stream_init;

// ---------------------------------------------------------------------------
extern "C" void kernel_launch(void* const* d_in, const int* in_sizes, int n_in,
                              void* d_out, int out_size)
{
    const float* x   = (const float*)d_in[0];
    const float* w_c = (const float*)d_in[1];
    const float* b_c = (const float*)d_in[2];
    const float* w_p = (const float*)d_in[3];
    const float* b_p = (const float*)d_in[4];
    float* out = (float*)d_out;

    void *qkvh_p, *attnh_p, *xh_p, *wcth_p, *wpth_p;
    cudaGetSymbolAddress(&qkvh_p, g_qkvh);
    cudaGetSymbolAddress(&attnh_p, g_attnh);
    cudaGetSymbolAddress(&xh_p, g_xh);
    cudaGetSymbolAddress(&wcth_p, g_wcth);
    cudaGetSymbolAddress(&wpth_p, g_wpth);
    __half* qkvh  = (__half*)qkvh_p;
    __half* attnh = (__half*)attnh_p;
    __half* xh    = (__half*)xh_p;
    __half* wcth  = (__half*)wcth_p;
    __half* wpth  = (__half*)wpth_p;

    static bool attr_done = false;
    if (!attr_done) {
        cudaFuncSetAttribute(gemm_f16_kernel,
                             cudaFuncAttributeMaxDynamicSharedMemorySize, GEMM_SMEM);
        cudaFuncSetAttribute(flash_f16_kernel,
                             cudaFuncAttributeMaxDynamicSharedMemorySize, FLASH_SMEM);
        attr_done = true;
    }

    if (g_streams_ok) {
        // Fork side streams off the capture-origin (default) stream
        cudaEventRecord(g_evFork, 0);
        cudaStreamWaitEvent(g_sA, g_evFork, 0);
        cudaStreamWaitEvent(g_sB, g_evFork, 0);

        // Prep: x->fp16 on stream 0; weight transposes on side streams
        round_f16_kernel<<<(MROWS * NX_ / 4 + 255) / 256, 256, 0, 0>>>(
            x, xh, MROWS * NX_ / 4);
        transpose_f16_kernel<<<dim3(C3 / 32, NX_ / 32), dim3(32, 8), 0, g_sA>>>(
            w_c, wcth, NX_, C3);
        cudaEventRecord(g_evWc, g_sA);
        transpose_f16_kernel<<<dim3(NST / 32, NX_ / 32), dim3(32, 8), 0, g_sB>>>(
            w_p, wpth, NX_, NST);
        cudaEventRecord(g_evWp, g_sB);

        // QKV projection (needs xh + wcth)
        cudaStreamWaitEvent(0, g_evWc, 0);
        gemm_f16_kernel<<<dim3(C3 / GBN, MROWS / GBM), 256, GEMM_SMEM, 0>>>(
            xh, wcth, b_c, nullptr, qkvh, 1, MROWS, C3, NX_);

        // Flash batch 0, then batch 1 on stream 0
        flash_f16_kernel<<<dim3(S_ / 128, NH, 1), 256, FLASH_SMEM, 0>>>(
            qkvh, attnh, 0);
        cudaEventRecord(g_evF0, 0);
        flash_f16_kernel<<<dim3(S_ / 128, NH, 1), 256, FLASH_SMEM, 0>>>(
            qkvh, attnh, 1);

        // Proj half 0 (rows of batch 0) on sA, overlapping flash batch 1
        cudaStreamWaitEvent(g_sA, g_evF0, 0);
        cudaStreamWaitEvent(g_sA, g_evWp, 0);
        gemm_f16_kernel<<<dim3(NST / GBN, (MROWS / 2) / GBM), 256, GEMM_SMEM, g_sA>>>(
            attnh, wpth, b_p, out, nullptr, 0, MROWS / 2, NST, NX_);
        cudaEventRecord(g_evP0, g_sA);

        // Proj half 1 (rows of batch 1) on stream 0 after flash batch 1
        cudaStreamWaitEvent(0, g_evWp, 0);
        gemm_f16_kernel<<<dim3(NST / GBN, (MROWS / 2) / GBM), 256, GEMM_SMEM, 0>>>(
            attnh + (size_t)(MROWS / 2) * NST, wpth, b_p,
            out + (size_t)(MROWS / 2) * NST, nullptr, 0, MROWS / 2, NST, NX_);

        // Join sA back into the origin stream
        cudaStreamWaitEvent(0, g_evP0, 0);
    } else {
        // Sequential fallback
        round_f16_kernel<<<(MROWS * NX_ / 4 + 255) / 256, 256>>>(
            x, xh, MROWS * NX_ / 4);
        transpose_f16_kernel<<<dim3(C3 / 32, NX_ / 32), dim3(32, 8)>>>(
            w_c, wcth, NX_, C3);
        transpose_f16_kernel<<<dim3(NST / 32, NX_ / 32), dim3(32, 8)>>>(
            w_p, wpth, NX_, NST);
        gemm_f16_kernel<<<dim3(C3 / GBN, MROWS / GBM), 256, GEMM_SMEM>>>(
            xh, wcth, b_c, nullptr, qkvh, 1, MROWS, C3, NX_);
        flash_f16_kernel<<<dim3(S_ / 128, NH, 1), 256, FLASH_SMEM>>>(qkvh, attnh, 0);
        flash_f16_kernel<<<dim3(S_ / 128, NH, 1), 256, FLASH_SMEM>>>(qkvh, attnh, 1);
        gemm_f16_kernel<<<dim3(NST / GBN, MROWS / GBM), 256, GEMM_SMEM>>>(
            attnh, wpth, b_p, out, nullptr, 0, MROWS, NST, NX_);
    }
}

// round 13
// speedup vs baseline: 1.0811x; 1.0811x over previous
#include <cuda_runtime.h>
#include <math_constants.h>
#include <cuda_fp16.h>
#include <cstdint>

#define B_    2
#define S_    2048
#define NX_   1024
#define NST   1024
#define NH    16
#define HD    64
#define MROWS 4096
#define C3    3072

// Scratch (no allocations allowed)
__device__ __half g_qkvh[MROWS * C3];   // [4096, 3072] q|k|v fp16
__device__ __half g_attnh[MROWS * NST]; // merged heads fp16
__device__ __half g_xh[MROWS * NX_];    // x fp16
__device__ __half g_wcth[C3 * NX_];     // w_c^T fp16
__device__ __half g_wpth[NST * NX_];    // w_p^T fp16

__device__ __forceinline__ uint32_t smem_u32(const void* p) {
    uint32_t a;
    asm("{ .reg .u64 t; cvta.to.shared.u64 t, %1; cvt.u32.u64 %0, t; }"
        : "=r"(a) : "l"(p));
    return a;
}
__device__ __forceinline__ uint32_t pack_h2(float lo, float hi) {
    uint32_t r;
    asm("cvt.rn.f16x2.f32 %0, %1, %2;" : "=r"(r) : "f"(hi), "f"(lo));
    return r;
}
__device__ __forceinline__ uint32_t ex2_h2(uint32_t h2) {
    uint32_t r;
    asm("ex2.approx.f16x2 %0, %1;" : "=r"(r) : "r"(h2));
    return r;
}
__device__ __forceinline__ float2 h2_to_f2(uint32_t h2) {
    __half2 h = *reinterpret_cast<__half2*>(&h2);
    return __half22float2(h);
}
#define CP_ASYNC16(smaddr, gptr) \
    asm volatile("cp.async.cg.shared.global [%0], [%1], 16;" \
                 :: "r"(smaddr), "l"(gptr) : "memory")
#define CP_COMMIT() asm volatile("cp.async.commit_group;" ::: "memory")
#define CP_WAIT1()  asm volatile("cp.async.wait_group 1;" ::: "memory")

#define MMA_F16(acc, a, b0, b1)                                                \
    asm volatile(                                                              \
        "mma.sync.aligned.m16n8k16.row.col.f32.f16.f16.f32 "                   \
        "{%0,%1,%2,%3}, {%4,%5,%6,%7}, {%8,%9}, {%0,%1,%2,%3};"                \
        : "+f"((acc)[0]), "+f"((acc)[1]), "+f"((acc)[2]), "+f"((acc)[3])       \
        : "r"((a)[0]), "r"((a)[1]), "r"((a)[2]), "r"((a)[3]),                  \
          "r"(b0), "r"(b1))

#define LDMX4(r0, r1, r2, r3, addr)                                            \
    asm volatile(                                                              \
        "ldmatrix.sync.aligned.m8n8.x4.shared.b16 {%0,%1,%2,%3}, [%4];"        \
        : "=r"(r0), "=r"(r1), "=r"(r2), "=r"(r3) : "r"(addr))

#define LDMX4T(r0, r1, r2, r3, addr)                                           \
    asm volatile(                                                              \
        "ldmatrix.sync.aligned.m8n8.x4.trans.shared.b16 {%0,%1,%2,%3}, [%4];"  \
        : "=r"(r0), "=r"(r1), "=r"(r2), "=r"(r3) : "r"(addr))

// ---------------------------------------------------------------------------
// Prep kernels
// ---------------------------------------------------------------------------
__global__ __launch_bounds__(256) void round_f16_kernel(
    const float* __restrict__ in, __half* __restrict__ out, int n4)
{
    int i = blockIdx.x * 256 + threadIdx.x;
    if (i < n4) {
        float4 v = ((const float4*)in)[i];
        uint2 o;
        o.x = pack_h2(v.x, v.y);
        o.y = pack_h2(v.z, v.w);
        ((uint2*)out)[i] = o;
    }
}

__global__ __launch_bounds__(256) void transpose_f16_kernel(
    const float* __restrict__ W, __half* __restrict__ WT, int K, int N)
{
    __shared__ float t[32][33];
    const int tx = threadIdx.x, ty = threadIdx.y;
    const int n0 = blockIdx.x * 32, k0 = blockIdx.y * 32;
    #pragma unroll
    for (int i = 0; i < 32; i += 8)
        t[ty + i][tx] = W[(size_t)(k0 + ty + i) * N + n0 + tx];
    __syncthreads();
    #pragma unroll
    for (int i = 0; i < 32; i += 8)
        WT[(size_t)(n0 + ty + i) * K + k0 + tx] = __float2half(t[tx][ty + i]);
}

// ---------------------------------------------------------------------------
// fp16 mma GEMM (R9/R11 config: BM=128, BN=128, BK=64, 8 warps, ping-pong
// frags, 3-stage cp.async, one barrier per chunk, 2 CTA/SM).
// ---------------------------------------------------------------------------
#define GBM 128
#define GBN 128
#define GBK 64
#define HP  72
#define TILE_H (128 * HP)
#define GEMM_SMEM (6 * TILE_H * 2)        // 110592 B

__global__ __launch_bounds__(256, 2) void gemm_f16_kernel(
    const __half* __restrict__ A, const __half* __restrict__ BT,
    const float* __restrict__ bias, float* __restrict__ C,
    __half* __restrict__ QH, int qkv_mode,
    int M, int N, int K)
{
    extern __shared__ __align__(16) __half smh[];
    const uint32_t smb = smem_u32(smh);

    const int tid = threadIdx.x;
    const int wid = tid >> 5, lane = tid & 31;
    const int gid = lane >> 2, tig = lane & 3;
    const int warp_m = wid & 1, warp_n = wid >> 1;

    const int m0 = blockIdx.y * GBM;
    const int n0 = blockIdx.x * GBN;

    const int cr = tid >> 1;
    const int cb = (tid & 1) << 3;

    const __half* Ap = A + (size_t)m0 * K;
    const __half* Bp = BT + (size_t)n0 * K;

    const int nchunk = K / GBK;

    const int mrow = lane & 15;
    const int kcolA = (lane >> 4) << 3;
    const int nrow = ((lane >> 4) << 3) + (lane & 7);
    const int kcolB = ((lane >> 3) & 1) << 3;

    float acc[4][4][4];
    #pragma unroll
    for (int i = 0; i < 4; i++)
        #pragma unroll
        for (int j = 0; j < 4; j++)
            #pragma unroll
            for (int r = 0; r < 4; r++) acc[i][j][r] = 0.0f;

    #define PREFETCH(kc, st) do {                                               \
        const uint32_t abase = smb + (st) * TILE_H * 2;                         \
        const uint32_t bbase = smb + (3 + (st)) * TILE_H * 2;                   \
        _Pragma("unroll")                                                       \
        for (int s = 0; s < 4; s++) {                                           \
            const int col = cb + s * 16;                                        \
            CP_ASYNC16(abase + (cr * HP + col) * 2,                             \
                       Ap + (size_t)cr * K + (kc) * GBK + col);                 \
            CP_ASYNC16(bbase + (cr * HP + col) * 2,                             \
                       Bp + (size_t)cr * K + (kc) * GBK + col);                 \
        }                                                                       \
    } while (0)

    PREFETCH(0, 0); CP_COMMIT();
    PREFETCH(1, 1); CP_COMMIT();

    uint32_t af[2][4][4], bf[2][2][4];

    #define LOAD_FRAGS(buf, Asb_, Bsb_, k0_) do {                               \
        _Pragma("unroll")                                                       \
        for (int i = 0; i < 4; i++) {                                           \
            const uint32_t a_ =                                                 \
                (Asb_) + ((warp_m * 64 + i * 16 + mrow) * HP + (k0_) + kcolA) * 2; \
            LDMX4(af[buf][i][0], af[buf][i][1], af[buf][i][2], af[buf][i][3], a_); \
        }                                                                       \
        _Pragma("unroll")                                                       \
        for (int j = 0; j < 2; j++) {                                           \
            const uint32_t b_ =                                                 \
                (Bsb_) + ((warp_n * 32 + j * 16 + nrow) * HP + (k0_) + kcolB) * 2; \
            LDMX4(bf[buf][j][0], bf[buf][j][1], bf[buf][j][2], bf[buf][j][3], b_); \
        }                                                                       \
    } while (0)

    #define MMA_GROUP(buf) do {                                                 \
        _Pragma("unroll")                                                       \
        for (int j = 0; j < 2; j++)                                             \
            _Pragma("unroll")                                                   \
            for (int i = 0; i < 4; i++) {                                       \
                MMA_F16(acc[i][2 * j],     af[buf][i], bf[buf][j][0], bf[buf][j][1]); \
                MMA_F16(acc[i][2 * j + 1], af[buf][i], bf[buf][j][2], bf[buf][j][3]); \
            }                                                                   \
    } while (0)

    for (int kc = 0; kc < nchunk; kc++) {
        const int st = kc % 3;
        CP_WAIT1();
        __syncthreads();

        const uint32_t Asb = smb + st * TILE_H * 2;
        const uint32_t Bsb = smb + (3 + st) * TILE_H * 2;

        LOAD_FRAGS(0, Asb, Bsb, 0);
        if (kc + 2 < nchunk) { PREFETCH(kc + 2, (kc + 2) % 3); }
        CP_COMMIT();

        #pragma unroll
        for (int g = 0; g < 4; g++) {
            if (g < 3) LOAD_FRAGS((g + 1) & 1, Asb, Bsb, (g + 1) * 16);
            MMA_GROUP(g & 1);
        }
    }

    if (qkv_mode) {
        #pragma unroll
        for (int i = 0; i < 4; i++) {
            const int r0 = m0 + warp_m * 64 + i * 16 + gid;
            #pragma unroll
            for (int j = 0; j < 4; j++) {
                const int col = n0 + warp_n * 32 + j * 8 + 2 * tig;
                const float bx = bias[col], by = bias[col + 1];
                *(uint32_t*)(QH + (size_t)r0 * C3 + col) =
                    pack_h2(acc[i][j][0] + bx, acc[i][j][1] + by);
                *(uint32_t*)(QH + (size_t)(r0 + 8) * C3 + col) =
                    pack_h2(acc[i][j][2] + bx, acc[i][j][3] + by);
            }
        }
    } else {
        #pragma unroll
        for (int i = 0; i < 4; i++) {
            const int r0 = m0 + warp_m * 64 + i * 16 + gid;
            #pragma unroll
            for (int j = 0; j < 4; j++) {
                const int col = n0 + warp_n * 32 + j * 8 + 2 * tig;
                const float bx = bias[col], by = bias[col + 1];
                float2 v0 = make_float2(acc[i][j][0] + bx, acc[i][j][1] + by);
                float2 v1 = make_float2(acc[i][j][2] + bx, acc[i][j][3] + by);
                *(float2*)(C + (size_t)r0 * N + col) = v0;
                *(float2*)(C + (size_t)(r0 + 8) * N + col) = v1;
            }
        }
    }
}

// ---------------------------------------------------------------------------
// Flash attention, fp16 mma + f16x2 exp. 3-stage KV pipeline, ONE barrier
// per tile (prefetch at top overwrites the stage consumed two iterations
// ago — safe after the top barrier). Full-batch grid (z = batch).
// Smem (halves): Q 128x72 | K 3x 64x72 | V 3x 64x72 = 73728 B. 2 CTA/SM.
// ---------------------------------------------------------------------------
#define KOFF 9216                            // halves
#define KVSTG 4608                           // halves per K or V stage
#define VOFF  (KOFF + 3 * KVSTG)
#define FLASH_SMEM ((VOFF + 3 * KVSTG) * 2)  // 73728 B

__global__ __launch_bounds__(256, 2) void flash_f16_kernel(
    const __half* __restrict__ qkvh, __half* __restrict__ attnh)
{
    extern __shared__ __align__(16) __half smh[];
    const uint32_t smb = smem_u32(smh);

    const int qb = (int)gridDim.x - 1 - (int)blockIdx.x;  // heavy first
    const int h  = blockIdx.y;
    const int b  = blockIdx.z;
    const int tid = threadIdx.x;
    const int wid = tid >> 5, lane = tid & 31;
    const int gid = lane >> 2, tig = lane & 3;

    const int hoff = h * HD;
    const __half* qptr = qkvh + (size_t)b * S_ * C3 + (size_t)qb * 128 * C3 + hoff;
    const __half* kptr = qkvh + (size_t)b * S_ * C3 + NST + hoff;
    const __half* vptr = qkvh + (size_t)b * S_ * C3 + 2 * NST + hoff;
    const float qls = 0.125f * 1.4426950408889634f;   // rsqrt(64)*log2(e)

    // Q tile (group 0): 128 rows x 64 halves
    {
        const int r = tid >> 1;
        const int cb = (tid & 1) << 3;
        #pragma unroll
        for (int s = 0; s < 4; s++) {
            const int c = cb + s * 16;
            CP_ASYNC16(smb + (r * HP + c) * 2, qptr + (size_t)r * C3 + c);
        }
        CP_COMMIT();
    }

    #define PREFETCH_KV(kt, st) do {                                            \
        const uint32_t kb = smb + (KOFF + (st) * KVSTG) * 2;                     \
        const uint32_t vb = smb + (VOFF + (st) * KVSTG) * 2;                     \
        const int r_ = tid >> 2;                                                 \
        _Pragma("unroll")                                                        \
        for (int s_ = 0; s_ < 2; s_++) {                                         \
            const int c_ = ((tid & 3) + 4 * s_) * 8;                             \
            CP_ASYNC16(kb + (r_ * HP + c_) * 2,                                  \
                       kptr + (size_t)((kt) * 64 + r_) * C3 + c_);               \
            CP_ASYNC16(vb + (r_ * HP + c_) * 2,                                  \
                       vptr + (size_t)((kt) * 64 + r_) * C3 + c_);               \
        }                                                                        \
    } while (0)

    PREFETCH_KV(0, 0); CP_COMMIT();
    PREFETCH_KV(1, 1); CP_COMMIT();

    float oacc[8][4];
    #pragma unroll
    for (int nb = 0; nb < 8; nb++)
        #pragma unroll
        for (int r = 0; r < 4; r++) oacc[nb][r] = 0.0f;
    float m0 = -1e30f, m1 = -1e30f, l0 = 0.0f, l1 = 0.0f;

    const int pr = wid * 16 + gid;
    const int grow0 = qb * 128 + pr;
    const int grow1 = grow0 + 8;

    const int mrow = lane & 15;
    const int kcolA = (lane >> 4) << 3;
    const int nrow = ((lane >> 4) << 3) + (lane & 7);
    const int kcolB = ((lane >> 3) & 1) << 3;
    const int l16 = lane & 15;
    const int chalf = (lane >> 4) << 3;

    const int nkt = 2 * qb + 2;
    for (int kt = 0; kt < nkt; kt++) {
        const int st = kt % 3;
        CP_WAIT1();
        __syncthreads();      // all warps done with tile kt-1; stage kt data in

        // prefetch into stage (kt+2)%3, consumed at iteration kt-1
        if (kt + 2 < nkt) { PREFETCH_KV(kt + 2, (kt + 2) % 3); }
        CP_COMMIT();

        const uint32_t Ksb = smb + (KOFF + st * KVSTG) * 2;
        const uint32_t vbase = smb + (VOFF + st * KVSTG) * 2;

        // S = Q K^T (fp16 mma, f32 acc) — raw, unscaled
        float sacc[8][4];
        #pragma unroll
        for (int nb = 0; nb < 8; nb++)
            #pragma unroll
            for (int r = 0; r < 4; r++) sacc[nb][r] = 0.0f;

        #pragma unroll
        for (int k0 = 0; k0 < 64; k0 += 16) {
            uint32_t qa[4];
            LDMX4(qa[0], qa[1], qa[2], qa[3],
                  smb + ((wid * 16 + mrow) * HP + k0 + kcolA) * 2);
            #pragma unroll
            for (int j = 0; j < 4; j++) {
                uint32_t b0, b1, b2, b3;
                LDMX4(b0, b1, b2, b3,
                      Ksb + ((j * 16 + nrow) * HP + k0 + kcolB) * 2);
                MMA_F16(sacc[2 * j],     qa, b0, b1);
                MMA_F16(sacc[2 * j + 1], qa, b2, b3);
            }
        }

        // causal mask on raw scores (diag-crossing tiles only)
        if (kt >= 2 * qb) {
            #pragma unroll
            for (int nb = 0; nb < 8; nb++) {
                const int c = kt * 64 + nb * 8 + 2 * tig;
                if (c > grow0)     sacc[nb][0] = -1e30f;
                if (c + 1 > grow0) sacc[nb][1] = -1e30f;
                if (c > grow1)     sacc[nb][2] = -1e30f;
                if (c + 1 > grow1) sacc[nb][3] = -1e30f;
            }
        }

        // row max over raw scores; to scaled (log2) domain once
        float mx0 = -1e30f, mx1 = -1e30f;
        #pragma unroll
        for (int nb = 0; nb < 8; nb++) {
            mx0 = fmaxf(mx0, fmaxf(sacc[nb][0], sacc[nb][1]));
            mx1 = fmaxf(mx1, fmaxf(sacc[nb][2], sacc[nb][3]));
        }
        mx0 = fmaxf(mx0, __shfl_xor_sync(0xffffffffu, mx0, 1));
        mx0 = fmaxf(mx0, __shfl_xor_sync(0xffffffffu, mx0, 2));
        mx1 = fmaxf(mx1, __shfl_xor_sync(0xffffffffu, mx1, 1));
        mx1 = fmaxf(mx1, __shfl_xor_sync(0xffffffffu, mx1, 2));
        const float mn0 = fmaxf(m0, mx0 * qls), mn1 = fmaxf(m1, mx1 * qls);
        const float al0 = exp2f(m0 - mn0), al1 = exp2f(m1 - mn1);

        // P = exp2(s*qls - mn) via ex2.approx.f16x2
        uint32_t plo[8], phi[8];
        float sum0 = 0.0f, sum1 = 0.0f;
        #pragma unroll
        for (int nb = 0; nb < 8; nb++) {
            const float d0 = fmaf(sacc[nb][0], qls, -mn0);
            const float d1 = fmaf(sacc[nb][1], qls, -mn0);
            const float d2 = fmaf(sacc[nb][2], qls, -mn1);
            const float d3 = fmaf(sacc[nb][3], qls, -mn1);
            plo[nb] = ex2_h2(pack_h2(d0, d1));
            phi[nb] = ex2_h2(pack_h2(d2, d3));
            const float2 f0 = h2_to_f2(plo[nb]);
            const float2 f1 = h2_to_f2(phi[nb]);
            sum0 += f0.x + f0.y;
            sum1 += f1.x + f1.y;
        }
        sum0 += __shfl_xor_sync(0xffffffffu, sum0, 1);
        sum0 += __shfl_xor_sync(0xffffffffu, sum0, 2);
        sum1 += __shfl_xor_sync(0xffffffffu, sum1, 1);
        sum1 += __shfl_xor_sync(0xffffffffu, sum1, 2);
        l0 = l0 * al0 + sum0;
        l1 = l1 * al1 + sum1;
        m0 = mn0; m1 = mn1;
        #pragma unroll
        for (int nb = 0; nb < 8; nb++) {
            oacc[nb][0] *= al0; oacc[nb][1] *= al0;
            oacc[nb][2] *= al1; oacc[nb][3] *= al1;
        }

        // PV: P fragments straight from plo/phi; V via ldmatrix.x4.trans
        #pragma unroll
        for (int nbp = 0; nbp < 4; nbp++) {
            uint32_t pa[4];
            pa[0] = plo[2 * nbp];
            pa[1] = phi[2 * nbp];
            pa[2] = plo[2 * nbp + 1];
            pa[3] = phi[2 * nbp + 1];
            const int k0 = nbp * 16;
            #pragma unroll
            for (int np = 0; np < 4; np++) {
                const int n0c = np * 16;
                uint32_t b0, b1, b2, b3;
                const uint32_t va =
                    vbase + ((k0 + l16) * HP + n0c + chalf) * 2;
                LDMX4T(b0, b1, b2, b3, va);
                MMA_F16(oacc[2 * np],     pa, b0, b1);
                MMA_F16(oacc[2 * np + 1], pa, b2, b3);
            }
        }
    }

    const float inv0 = 1.0f / l0, inv1 = 1.0f / l1;
    __half* orow0 = attnh + ((size_t)b * S_ + grow0) * NST + hoff;
    __half* orow1 = attnh + ((size_t)b * S_ + grow1) * NST + hoff;
    #pragma unroll
    for (int nb = 0; nb < 8; nb++) {
        const int c = nb * 8 + 2 * tig;
        *(uint32_t*)(orow0 + c) = pack_h2(oacc[nb][0] * inv0, oacc[nb][1] * inv0);
        *(uint32_t*)(orow1 + c) = pack_h2(oacc[nb][2] * inv1, oacc[nb][3] * inv1);
    }
}

// ---------------------------------------------------------------------------
extern "C" void kernel_launch(void* const* d_in, const int* in_sizes, int n_in,
                              void* d_out, int out_size)
{
    const float* x   = (const float*)d_in[0];
    const float* w_c = (const float*)d_in[1];
    const float* b_c = (const float*)d_in[2];
    const float* w_p = (const float*)d_in[3];
    const float* b_p = (const float*)d_in[4];
    float* out = (float*)d_out;

    void *qkvh_p, *attnh_p, *xh_p, *wcth_p, *wpth_p;
    cudaGetSymbolAddress(&qkvh_p, g_qkvh);
    cudaGetSymbolAddress(&attnh_p, g_attnh);
    cudaGetSymbolAddress(&xh_p, g_xh);
    cudaGetSymbolAddress(&wcth_p, g_wcth);
    cudaGetSymbolAddress(&wpth_p, g_wpth);
    __half* qkvh  = (__half*)qkvh_p;
    __half* attnh = (__half*)attnh_p;
    __half* xh    = (__half*)xh_p;
    __half* wcth  = (__half*)wcth_p;
    __half* wpth  = (__half*)wpth_p;

    static bool attr_done = false;
    if (!attr_done) {
        cudaFuncSetAttribute(gemm_f16_kernel,
                             cudaFuncAttributeMaxDynamicSharedMemorySize, GEMM_SMEM);
        cudaFuncSetAttribute(flash_f16_kernel,
                             cudaFuncAttributeMaxDynamicSharedMemorySize, FLASH_SMEM);
        attr_done = true;
    }

    // 0) Convert x and weights to fp16 (weights transposed)
    round_f16_kernel<<<(MROWS * NX_ / 4 + 255) / 256, 256>>>(x, xh, MROWS * NX_ / 4);
    transpose_f16_kernel<<<dim3(C3 / 32, NX_ / 32), dim3(32, 8)>>>(w_c, wcth, NX_, C3);
    transpose_f16_kernel<<<dim3(NST / 32, NX_ / 32), dim3(32, 8)>>>(w_p, wpth, NX_, NST);

    // 1) QKV projection -> fp16 q|k|v
    gemm_f16_kernel<<<dim3(C3 / GBN, MROWS / GBM), 256, GEMM_SMEM>>>(
        xh, wcth, b_c, nullptr, qkvh, 1, MROWS, C3, NX_);

    // 2) Flash attention (fp16 mma, f16x2 exp, 3-stage pipe) -> fp16 heads
    flash_f16_kernel<<<dim3(S_ / 128, NH, B_), 256, FLASH_SMEM>>>(qkvh, attnh);

    // 3) Output projection -> f32 out
    gemm_f16_kernel<<<dim3(NST / GBN, MROWS / GBM), 256, GEMM_SMEM>>>(
        attnh, wpth, b_p, out, nullptr, 0, MROWS, NST, NX_);
}

// round 14
// speedup vs baseline: 1.1323x; 1.0474x over previous
#include <cuda_runtime.h>
#include <math_constants.h>
#include <cuda_fp16.h>
#include <cstdint>

#define B_    2
#define S_    2048
#define NX_   1024
#define NST   1024
#define NH    16
#define HD    64
#define MROWS 4096
#define C3    3072

// Scratch (no allocations allowed)
__device__ __half g_qkvh[MROWS * C3];   // [4096, 3072] q|k|v fp16
__device__ __half g_attnh[MROWS * NST]; // merged heads fp16
__device__ __half g_xh[MROWS * NX_];    // x fp16
__device__ __half g_wcth[C3 * NX_];     // w_c^T fp16
__device__ __half g_wpth[NST * NX_];    // w_p^T fp16

__device__ __forceinline__ uint32_t smem_u32(const void* p) {
    uint32_t a;
    asm("{ .reg .u64 t; cvta.to.shared.u64 t, %1; cvt.u32.u64 %0, t; }"
        : "=r"(a) : "l"(p));
    return a;
}
__device__ __forceinline__ uint32_t pack_h2(float lo, float hi) {
    uint32_t r;
    asm("cvt.rn.f16x2.f32 %0, %1, %2;" : "=r"(r) : "f"(hi), "f"(lo));
    return r;
}
__device__ __forceinline__ uint32_t ex2_h2(uint32_t h2) {
    uint32_t r;
    asm("ex2.approx.f16x2 %0, %1;" : "=r"(r) : "r"(h2));
    return r;
}
__device__ __forceinline__ float2 h2_to_f2(uint32_t h2) {
    __half2 h = *reinterpret_cast<__half2*>(&h2);
    return __half22float2(h);
}
#define CP_ASYNC16(smaddr, gptr) \
    asm volatile("cp.async.cg.shared.global [%0], [%1], 16;" \
                 :: "r"(smaddr), "l"(gptr) : "memory")
#define CP_COMMIT() asm volatile("cp.async.commit_group;" ::: "memory")
#define CP_WAIT1()  asm volatile("cp.async.wait_group 1;" ::: "memory")

#define MMA_F16(acc, a, b0, b1)                                                \
    asm volatile(                                                              \
        "mma.sync.aligned.m16n8k16.row.col.f32.f16.f16.f32 "                   \
        "{%0,%1,%2,%3}, {%4,%5,%6,%7}, {%8,%9}, {%0,%1,%2,%3};"                \
        : "+f"((acc)[0]), "+f"((acc)[1]), "+f"((acc)[2]), "+f"((acc)[3])       \
        : "r"((a)[0]), "r"((a)[1]), "r"((a)[2]), "r"((a)[3]),                  \
          "r"(b0), "r"(b1))

#define LDMX4(r0, r1, r2, r3, addr)                                            \
    asm volatile(                                                              \
        "ldmatrix.sync.aligned.m8n8.x4.shared.b16 {%0,%1,%2,%3}, [%4];"        \
        : "=r"(r0), "=r"(r1), "=r"(r2), "=r"(r3) : "r"(addr))

#define LDMX4T(r0, r1, r2, r3, addr)                                           \
    asm volatile(                                                              \
        "ldmatrix.sync.aligned.m8n8.x4.trans.shared.b16 {%0,%1,%2,%3}, [%4];"  \
        : "=r"(r0), "=r"(r1), "=r"(r2), "=r"(r3) : "r"(addr))

// ---------------------------------------------------------------------------
// Fused prep: ONE launch does x->fp16 (blocks [0, XBLKS)), w_c transpose
// (blocks [XBLKS, XBLKS+WCBLKS)), w_p transpose (rest). Removes 2 launch
// gaps and overlaps three memory-bound phases.
// ---------------------------------------------------------------------------
#define XBLKS  (MROWS * NX_ / 4 / 256)          // 4096
#define WCBLKS ((C3 / 32) * (NX_ / 32))         // 3072
#define WPBLKS ((NST / 32) * (NX_ / 32))        // 1024
#define PREP_BLOCKS (XBLKS + WCBLKS + WPBLKS)   // 8192

__device__ __forceinline__ void transpose_tile_f16(
    const float* __restrict__ W, __half* __restrict__ WT,
    int K, int N, int n0, int k0, int tid, float (*t)[33])
{
    const int tx = tid & 31, ty = tid >> 5;
    #pragma unroll
    for (int i = 0; i < 32; i += 8)
        t[ty + i][tx] = W[(size_t)(k0 + ty + i) * N + n0 + tx];
    __syncthreads();
    #pragma unroll
    for (int i = 0; i < 32; i += 8)
        WT[(size_t)(n0 + ty + i) * K + k0 + tx] = __float2half(t[tx][ty + i]);
}

__global__ __launch_bounds__(256) void prep_kernel(
    const float* __restrict__ x, __half* __restrict__ xh,
    const float* __restrict__ w_c, __half* __restrict__ wcth,
    const float* __restrict__ w_p, __half* __restrict__ wpth)
{
    __shared__ float t[32][33];
    const int bid = blockIdx.x;
    const int tid = threadIdx.x;

    if (bid < XBLKS) {
        const int i = bid * 256 + tid;
        float4 v = ((const float4*)x)[i];
        uint2 o;
        o.x = pack_h2(v.x, v.y);
        o.y = pack_h2(v.z, v.w);
        ((uint2*)xh)[i] = o;
    } else if (bid < XBLKS + WCBLKS) {
        const int id = bid - XBLKS;
        const int n0 = (id % (C3 / 32)) * 32;
        const int k0 = (id / (C3 / 32)) * 32;
        transpose_tile_f16(w_c, wcth, NX_, C3, n0, k0, tid, t);
    } else {
        const int id = bid - XBLKS - WCBLKS;
        const int n0 = (id % (NST / 32)) * 32;
        const int k0 = (id / (NST / 32)) * 32;
        transpose_tile_f16(w_p, wpth, NX_, NST, n0, k0, tid, t);
    }
}

// ---------------------------------------------------------------------------
// fp16 mma GEMM (R9/R11 config: BM=128, BN=128, BK=64, 8 warps, ping-pong
// frags, 3-stage cp.async, one barrier per chunk, 2 CTA/SM).
// ---------------------------------------------------------------------------
#define GBM 128
#define GBN 128
#define GBK 64
#define HP  72
#define TILE_H (128 * HP)
#define GEMM_SMEM (6 * TILE_H * 2)        // 110592 B

__global__ __launch_bounds__(256, 2) void gemm_f16_kernel(
    const __half* __restrict__ A, const __half* __restrict__ BT,
    const float* __restrict__ bias, float* __restrict__ C,
    __half* __restrict__ QH, int qkv_mode,
    int M, int N, int K)
{
    extern __shared__ __align__(16) __half smh[];
    const uint32_t smb = smem_u32(smh);

    const int tid = threadIdx.x;
    const int wid = tid >> 5, lane = tid & 31;
    const int gid = lane >> 2, tig = lane & 3;
    const int warp_m = wid & 1, warp_n = wid >> 1;

    const int m0 = blockIdx.y * GBM;
    const int n0 = blockIdx.x * GBN;

    const int cr = tid >> 1;
    const int cb = (tid & 1) << 3;

    const __half* Ap = A + (size_t)m0 * K;
    const __half* Bp = BT + (size_t)n0 * K;

    const int nchunk = K / GBK;

    const int mrow = lane & 15;
    const int kcolA = (lane >> 4) << 3;
    const int nrow = ((lane >> 4) << 3) + (lane & 7);
    const int kcolB = ((lane >> 3) & 1) << 3;

    float acc[4][4][4];
    #pragma unroll
    for (int i = 0; i < 4; i++)
        #pragma unroll
        for (int j = 0; j < 4; j++)
            #pragma unroll
            for (int r = 0; r < 4; r++) acc[i][j][r] = 0.0f;

    #define PREFETCH(kc, st) do {                                               \
        const uint32_t abase = smb + (st) * TILE_H * 2;                         \
        const uint32_t bbase = smb + (3 + (st)) * TILE_H * 2;                   \
        _Pragma("unroll")                                                       \
        for (int s = 0; s < 4; s++) {                                           \
            const int col = cb + s * 16;                                        \
            CP_ASYNC16(abase + (cr * HP + col) * 2,                             \
                       Ap + (size_t)cr * K + (kc) * GBK + col);                 \
            CP_ASYNC16(bbase + (cr * HP + col) * 2,                             \
                       Bp + (size_t)cr * K + (kc) * GBK + col);                 \
        }                                                                       \
    } while (0)

    PREFETCH(0, 0); CP_COMMIT();
    PREFETCH(1, 1); CP_COMMIT();

    uint32_t af[2][4][4], bf[2][2][4];

    #define LOAD_FRAGS(buf, Asb_, Bsb_, k0_) do {                               \
        _Pragma("unroll")                                                       \
        for (int i = 0; i < 4; i++) {                                           \
            const uint32_t a_ =                                                 \
                (Asb_) + ((warp_m * 64 + i * 16 + mrow) * HP + (k0_) + kcolA) * 2; \
            LDMX4(af[buf][i][0], af[buf][i][1], af[buf][i][2], af[buf][i][3], a_); \
        }                                                                       \
        _Pragma("unroll")                                                       \
        for (int j = 0; j < 2; j++) {                                           \
            const uint32_t b_ =                                                 \
                (Bsb_) + ((warp_n * 32 + j * 16 + nrow) * HP + (k0_) + kcolB) * 2; \
            LDMX4(bf[buf][j][0], bf[buf][j][1], bf[buf][j][2], bf[buf][j][3], b_); \
        }                                                                       \
    } while (0)

    #define MMA_GROUP(buf) do {                                                 \
        _Pragma("unroll")                                                       \
        for (int j = 0; j < 2; j++)                                             \
            _Pragma("unroll")                                                   \
            for (int i = 0; i < 4; i++) {                                       \
                MMA_F16(acc[i][2 * j],     af[buf][i], bf[buf][j][0], bf[buf][j][1]); \
                MMA_F16(acc[i][2 * j + 1], af[buf][i], bf[buf][j][2], bf[buf][j][3]); \
            }                                                                   \
    } while (0)

    for (int kc = 0; kc < nchunk; kc++) {
        const int st = kc % 3;
        CP_WAIT1();
        __syncthreads();

        const uint32_t Asb = smb + st * TILE_H * 2;
        const uint32_t Bsb = smb + (3 + st) * TILE_H * 2;

        LOAD_FRAGS(0, Asb, Bsb, 0);
        if (kc + 2 < nchunk) { PREFETCH(kc + 2, (kc + 2) % 3); }
        CP_COMMIT();

        #pragma unroll
        for (int g = 0; g < 4; g++) {
            if (g < 3) LOAD_FRAGS((g + 1) & 1, Asb, Bsb, (g + 1) * 16);
            MMA_GROUP(g & 1);
        }
    }

    if (qkv_mode) {
        #pragma unroll
        for (int i = 0; i < 4; i++) {
            const int r0 = m0 + warp_m * 64 + i * 16 + gid;
            #pragma unroll
            for (int j = 0; j < 4; j++) {
                const int col = n0 + warp_n * 32 + j * 8 + 2 * tig;
                const float bx = bias[col], by = bias[col + 1];
                *(uint32_t*)(QH + (size_t)r0 * C3 + col) =
                    pack_h2(acc[i][j][0] + bx, acc[i][j][1] + by);
                *(uint32_t*)(QH + (size_t)(r0 + 8) * C3 + col) =
                    pack_h2(acc[i][j][2] + bx, acc[i][j][3] + by);
            }
        }
    } else {
        #pragma unroll
        for (int i = 0; i < 4; i++) {
            const int r0 = m0 + warp_m * 64 + i * 16 + gid;
            #pragma unroll
            for (int j = 0; j < 4; j++) {
                const int col = n0 + warp_n * 32 + j * 8 + 2 * tig;
                const float bx = bias[col], by = bias[col + 1];
                float2 v0 = make_float2(acc[i][j][0] + bx, acc[i][j][1] + by);
                float2 v1 = make_float2(acc[i][j][2] + bx, acc[i][j][3] + by);
                *(float2*)(C + (size_t)r0 * N + col) = v0;
                *(float2*)(C + (size_t)(r0 + 8) * N + col) = v1;
            }
        }
    }
}

// ---------------------------------------------------------------------------
// Flash attention (R11 exact: fp16 mma, f16x2 exp, 2-stage KV pipeline).
// Smem (halves): Q 128x72 | K 2x 64x72 | V 2x 64x72 = 55296 B. 2 CTA/SM.
// ---------------------------------------------------------------------------
#define KOFF 9216                            // halves
#define KVSTG 4608                           // halves per K or V stage
#define VOFF  (KOFF + 2 * KVSTG)
#define FLASH_SMEM ((VOFF + 2 * KVSTG) * 2)  // 55296 B

__global__ __launch_bounds__(256, 2) void flash_f16_kernel(
    const __half* __restrict__ qkvh, __half* __restrict__ attnh)
{
    extern __shared__ __align__(16) __half smh[];
    const uint32_t smb = smem_u32(smh);

    const int qb = (int)gridDim.x - 1 - (int)blockIdx.x;  // heavy first
    const int h  = blockIdx.y;
    const int b  = blockIdx.z;
    const int tid = threadIdx.x;
    const int wid = tid >> 5, lane = tid & 31;
    const int gid = lane >> 2, tig = lane & 3;

    const int hoff = h * HD;
    const __half* qptr = qkvh + (size_t)b * S_ * C3 + (size_t)qb * 128 * C3 + hoff;
    const __half* kptr = qkvh + (size_t)b * S_ * C3 + NST + hoff;
    const __half* vptr = qkvh + (size_t)b * S_ * C3 + 2 * NST + hoff;
    const float qls = 0.125f * 1.4426950408889634f;   // rsqrt(64)*log2(e)

    // Q tile (group 0): 128 rows x 64 halves
    {
        const int r = tid >> 1;
        const int cb = (tid & 1) << 3;
        #pragma unroll
        for (int s = 0; s < 4; s++) {
            const int c = cb + s * 16;
            CP_ASYNC16(smb + (r * HP + c) * 2, qptr + (size_t)r * C3 + c);
        }
        CP_COMMIT();
    }

    #define PREFETCH_KV(kt, st) do {                                            \
        const uint32_t kb = smb + (KOFF + (st) * KVSTG) * 2;                     \
        const uint32_t vb = smb + (VOFF + (st) * KVSTG) * 2;                     \
        const int r_ = tid >> 2;                                                 \
        _Pragma("unroll")                                                        \
        for (int s_ = 0; s_ < 2; s_++) {                                         \
            const int c_ = ((tid & 3) + 4 * s_) * 8;                             \
            CP_ASYNC16(kb + (r_ * HP + c_) * 2,                                  \
                       kptr + (size_t)((kt) * 64 + r_) * C3 + c_);               \
            CP_ASYNC16(vb + (r_ * HP + c_) * 2,                                  \
                       vptr + (size_t)((kt) * 64 + r_) * C3 + c_);               \
        }                                                                        \
    } while (0)

    PREFETCH_KV(0, 0); CP_COMMIT();
    PREFETCH_KV(1, 1); CP_COMMIT();

    float oacc[8][4];
    #pragma unroll
    for (int nb = 0; nb < 8; nb++)
        #pragma unroll
        for (int r = 0; r < 4; r++) oacc[nb][r] = 0.0f;
    float m0 = -1e30f, m1 = -1e30f, l0 = 0.0f, l1 = 0.0f;

    const int pr = wid * 16 + gid;
    const int grow0 = qb * 128 + pr;
    const int grow1 = grow0 + 8;

    const int mrow = lane & 15;
    const int kcolA = (lane >> 4) << 3;
    const int nrow = ((lane >> 4) << 3) + (lane & 7);
    const int kcolB = ((lane >> 3) & 1) << 3;
    const int l16 = lane & 15;
    const int chalf = (lane >> 4) << 3;

    const int nkt = 2 * qb + 2;
    for (int kt = 0; kt < nkt; kt++) {
        const int st = kt & 1;
        CP_WAIT1();
        __syncthreads();

        const uint32_t Ksb = smb + (KOFF + st * KVSTG) * 2;
        const uint32_t vbase = smb + (VOFF + st * KVSTG) * 2;

        // S = Q K^T (fp16 mma, f32 acc) — raw, unscaled
        float sacc[8][4];
        #pragma unroll
        for (int nb = 0; nb < 8; nb++)
            #pragma unroll
            for (int r = 0; r < 4; r++) sacc[nb][r] = 0.0f;

        #pragma unroll
        for (int k0 = 0; k0 < 64; k0 += 16) {
            uint32_t qa[4];
            LDMX4(qa[0], qa[1], qa[2], qa[3],
                  smb + ((wid * 16 + mrow) * HP + k0 + kcolA) * 2);
            #pragma unroll
            for (int j = 0; j < 4; j++) {
                uint32_t b0, b1, b2, b3;
                LDMX4(b0, b1, b2, b3,
                      Ksb + ((j * 16 + nrow) * HP + k0 + kcolB) * 2);
                MMA_F16(sacc[2 * j],     qa, b0, b1);
                MMA_F16(sacc[2 * j + 1], qa, b2, b3);
            }
        }

        // causal mask on raw scores (diag-crossing tiles only)
        if (kt >= 2 * qb) {
            #pragma unroll
            for (int nb = 0; nb < 8; nb++) {
                const int c = kt * 64 + nb * 8 + 2 * tig;
                if (c > grow0)     sacc[nb][0] = -1e30f;
                if (c + 1 > grow0) sacc[nb][1] = -1e30f;
                if (c > grow1)     sacc[nb][2] = -1e30f;
                if (c + 1 > grow1) sacc[nb][3] = -1e30f;
            }
        }

        // row max over raw scores; to scaled (log2) domain once
        float mx0 = -1e30f, mx1 = -1e30f;
        #pragma unroll
        for (int nb = 0; nb < 8; nb++) {
            mx0 = fmaxf(mx0, fmaxf(sacc[nb][0], sacc[nb][1]));
            mx1 = fmaxf(mx1, fmaxf(sacc[nb][2], sacc[nb][3]));
        }
        mx0 = fmaxf(mx0, __shfl_xor_sync(0xffffffffu, mx0, 1));
        mx0 = fmaxf(mx0, __shfl_xor_sync(0xffffffffu, mx0, 2));
        mx1 = fmaxf(mx1, __shfl_xor_sync(0xffffffffu, mx1, 1));
        mx1 = fmaxf(mx1, __shfl_xor_sync(0xffffffffu, mx1, 2));
        const float mn0 = fmaxf(m0, mx0 * qls), mn1 = fmaxf(m1, mx1 * qls);
        const float al0 = exp2f(m0 - mn0), al1 = exp2f(m1 - mn1);

        // P = exp2(s*qls - mn) via ex2.approx.f16x2
        uint32_t plo[8], phi[8];
        float sum0 = 0.0f, sum1 = 0.0f;
        #pragma unroll
        for (int nb = 0; nb < 8; nb++) {
            const float d0 = fmaf(sacc[nb][0], qls, -mn0);
            const float d1 = fmaf(sacc[nb][1], qls, -mn0);
            const float d2 = fmaf(sacc[nb][2], qls, -mn1);
            const float d3 = fmaf(sacc[nb][3], qls, -mn1);
            plo[nb] = ex2_h2(pack_h2(d0, d1));
            phi[nb] = ex2_h2(pack_h2(d2, d3));
            const float2 f0 = h2_to_f2(plo[nb]);
            const float2 f1 = h2_to_f2(phi[nb]);
            sum0 += f0.x + f0.y;
            sum1 += f1.x + f1.y;
        }
        sum0 += __shfl_xor_sync(0xffffffffu, sum0, 1);
        sum0 += __shfl_xor_sync(0xffffffffu, sum0, 2);
        sum1 += __shfl_xor_sync(0xffffffffu, sum1, 1);
        sum1 += __shfl_xor_sync(0xffffffffu, sum1, 2);
        l0 = l0 * al0 + sum0;
        l1 = l1 * al1 + sum1;
        m0 = mn0; m1 = mn1;
        #pragma unroll
        for (int nb = 0; nb < 8; nb++) {
            oacc[nb][0] *= al0; oacc[nb][1] *= al0;
            oacc[nb][2] *= al1; oacc[nb][3] *= al1;
        }

        // PV: P fragments straight from plo/phi; V via ldmatrix.x4.trans
        #pragma unroll
        for (int nbp = 0; nbp < 4; nbp++) {
            uint32_t pa[4];
            pa[0] = plo[2 * nbp];
            pa[1] = phi[2 * nbp];
            pa[2] = plo[2 * nbp + 1];
            pa[3] = phi[2 * nbp + 1];
            const int k0 = nbp * 16;
            #pragma unroll
            for (int np = 0; np < 4; np++) {
                const int n0c = np * 16;
                uint32_t b0, b1, b2, b3;
                const uint32_t va =
                    vbase + ((k0 + l16) * HP + n0c + chalf) * 2;
                LDMX4T(b0, b1, b2, b3, va);
                MMA_F16(oacc[2 * np],     pa, b0, b1);
                MMA_F16(oacc[2 * np + 1], pa, b2, b3);
            }
        }

        __syncthreads();
        if (kt + 2 < nkt) { PREFETCH_KV(kt + 2, st); }
        CP_COMMIT();
    }

    const float inv0 = 1.0f / l0, inv1 = 1.0f / l1;
    __half* orow0 = attnh + ((size_t)b * S_ + grow0) * NST + hoff;
    __half* orow1 = attnh + ((size_t)b * S_ + grow1) * NST + hoff;
    #pragma unroll
    for (int nb = 0; nb < 8; nb++) {
        const int c = nb * 8 + 2 * tig;
        *(uint32_t*)(orow0 + c) = pack_h2(oacc[nb][0] * inv0, oacc[nb][1] * inv0);
        *(uint32_t*)(orow1 + c) = pack_h2(oacc[nb][2] * inv1, oacc[nb][3] * inv1);
    }
}

// ---------------------------------------------------------------------------
extern "C" void kernel_launch(void* const* d_in, const int* in_sizes, int n_in,
                              void* d_out, int out_size)
{
    const float* x   = (const float*)d_in[0];
    const float* w_c = (const float*)d_in[1];
    const float* b_c = (const float*)d_in[2];
    const float* w_p = (const float*)d_in[3];
    const float* b_p = (const float*)d_in[4];
    float* out = (float*)d_out;

    void *qkvh_p, *attnh_p, *xh_p, *wcth_p, *wpth_p;
    cudaGetSymbolAddress(&qkvh_p, g_qkvh);
    cudaGetSymbolAddress(&attnh_p, g_attnh);
    cudaGetSymbolAddress(&xh_p, g_xh);
    cudaGetSymbolAddress(&wcth_p, g_wcth);
    cudaGetSymbolAddress(&wpth_p, g_wpth);
    __half* qkvh  = (__half*)qkvh_p;
    __half* attnh = (__half*)attnh_p;
    __half* xh    = (__half*)xh_p;
    __half* wcth  = (__half*)wcth_p;
    __half* wpth  = (__half*)wpth_p;

    static bool attr_done = false;
    if (!attr_done) {
        cudaFuncSetAttribute(gemm_f16_kernel,
                             cudaFuncAttributeMaxDynamicSharedMemorySize, GEMM_SMEM);
        cudaFuncSetAttribute(flash_f16_kernel,
                             cudaFuncAttributeMaxDynamicSharedMemorySize, FLASH_SMEM);
        attr_done = true;
    }

    // 0) Fused prep: x->fp16 + both weight transposes in ONE launch
    prep_kernel<<<PREP_BLOCKS, 256>>>(x, xh, w_c, wcth, w_p, wpth);

    // 1) QKV projection -> fp16 q|k|v
    gemm_f16_kernel<<<dim3(C3 / GBN, MROWS / GBM), 256, GEMM_SMEM>>>(
        xh, wcth, b_c, nullptr, qkvh, 1, MROWS, C3, NX_);

    // 2) Flash attention (fp16 mma, f16x2 exp) -> fp16 heads
    flash_f16_kernel<<<dim3(S_ / 128, NH, B_), 256, FLASH_SMEM>>>(qkvh, attnh);

    // 3) Output projection -> f32 out
    gemm_f16_kernel<<<dim3(NST / GBN, MROWS / GBM), 256, GEMM_SMEM>>>(
        attnh, wpth, b_p, out, nullptr, 0, MROWS, NST, NX_);
}